// round 13
// baseline (speedup 1.0000x reference)
#include <cuda_runtime.h>
#include <cuda_fp16.h>
#include <cstdint>

#define B_      2
#define CIN     256
#define Hdim    128
#define Wdim    128
#define KQ      128
#define HW      16384
#define NTOT    21504   // 16384 + 4096 + 1024
#define SCALE   0.08838834764831845f
#define PADW    130
#define PADN    16900   // 130*130

#define SMEM_BYTES 147456   // 3 stages x 48KB
#define SW(o) ((uint32_t)(o) ^ ((((uint32_t)(o)) >> 3) & 0x70u))

// ---------------- device scratch ----------------
__device__ __half g_fp_hi[B_ * PADN * CIN];
__device__ __half g_fp_lo[B_ * PADN * CIN];
__device__ __half g_w_hi[9 * KQ * CIN];
__device__ __half g_kw_hi[KQ * KQ];
__device__ __half g_qw_hi[KQ * KQ];
__device__ __half g_keys_h[B_ * HW * KQ];          // keys in fp16 (gathered by logits)
__device__ float  g_qrs[B_ * HW * KQ];             // queries fp32
__device__ __half g_k2_h[B_ * 4096 * KQ], g_k4_h[B_ * 1024 * KQ];
__device__ float  g_q2[B_ * 4096 * KQ],  g_q4[B_ * 1024 * KQ];

// ---------------- helpers ----------------
__device__ __forceinline__ uint32_t smem_u32(const void* p) {
    uint32_t a;
    asm("{ .reg .u64 t; cvta.to.shared.u64 t, %1; cvt.u32.u64 %0, t; }" : "=r"(a) : "l"(p));
    return a;
}
__device__ __forceinline__ void cp16(uint32_t dst, const void* src) {
    asm volatile("cp.async.cg.shared.global [%0], [%1], 16;" :: "r"(dst), "l"(src) : "memory");
}
#define CP_COMMIT() asm volatile("cp.async.commit_group;" ::: "memory")
#define CP_WAIT(n)  asm volatile("cp.async.wait_group %0;" :: "n"(n) : "memory")

__device__ __forceinline__ void ldsm_x4(uint32_t* r, uint32_t addr) {
    asm volatile("ldmatrix.sync.aligned.m8n8.x4.shared.b16 {%0,%1,%2,%3}, [%4];"
                 : "=r"(r[0]), "=r"(r[1]), "=r"(r[2]), "=r"(r[3]) : "r"(addr));
}
__device__ __forceinline__ void ldsm_x2(uint32_t* r, uint32_t addr) {
    asm volatile("ldmatrix.sync.aligned.m8n8.x2.shared.b16 {%0,%1}, [%2];"
                 : "=r"(r[0]), "=r"(r[1]) : "r"(addr));
}
// fp16 inputs, fp32 accumulator
__device__ __forceinline__ void mma_f32(float* c, const uint32_t* a, const uint32_t* b) {
    asm volatile("mma.sync.aligned.m16n8k16.row.col.f32.f16.f16.f32 "
                 "{%0,%1,%2,%3}, {%4,%5,%6,%7}, {%8,%9}, {%0,%1,%2,%3};"
                 : "+f"(c[0]), "+f"(c[1]), "+f"(c[2]), "+f"(c[3])
                 : "r"(a[0]), "r"(a[1]), "r"(a[2]), "r"(a[3]), "r"(b[0]), "r"(b[1]));
}
// fp16 inputs, fp16 accumulator (low-order term; magnitudes tiny)
__device__ __forceinline__ void mma_f16(uint32_t* c, const uint32_t* a, const uint32_t* b) {
    asm volatile("mma.sync.aligned.m16n8k16.row.col.f16.f16.f16.f16 "
                 "{%0,%1}, {%2,%3,%4,%5}, {%6,%7}, {%0,%1};"
                 : "+r"(c[0]), "+r"(c[1])
                 : "r"(a[0]), "r"(a[1]), "r"(a[2]), "r"(a[3]), "r"(b[0]), "r"(b[1]));
}
__device__ __forceinline__ uint32_t pack2h(__half a, __half b) {
    return (uint32_t)__half_as_ushort(a) | ((uint32_t)__half_as_ushort(b) << 16);
}
__device__ __forceinline__ float lo_half(uint32_t r) {
    return __half2float(__ushort_as_half((unsigned short)(r & 0xffffu)));
}
__device__ __forceinline__ float hi_half(uint32_t r) {
    return __half2float(__ushort_as_half((unsigned short)(r >> 16)));
}

// Stage 3 tiles (A_hi, A_lo, B_hi), each [128 rows x 64 fp16] SW128-swizzled. 48KB.
// 512 threads: 3072 cp16 ops -> 6 per thread.
__device__ __forceinline__ void stage_tiles(uint32_t sdst,
    const __half* a_hi, const __half* a_lo, const __half* b_hi,
    int a_stride, int b_stride, int tid)
{
    #pragma unroll
    for (int s = 0; s < 6; s++) {
        int i = tid + s * 512;
        int tile = i >> 10, j = i & 1023, r = j >> 3, c16 = j & 7;
        const __half* src;
        if (tile == 0)      src = a_hi + (size_t)r * a_stride;
        else if (tile == 1) src = a_lo + (size_t)r * a_stride;
        else                src = b_hi + (size_t)r * b_stride;
        cp16(sdst + tile * 16384 + SW(r * 128 + c16 * 16), src + c16 * 8);
    }
}

// One 128x128x64 split-GEMM step, warp tile M=32 x N=32: ah*bh (f32) + al*bh (f16).
__device__ __forceinline__ void compute_tile2(float acc[2][4][4], uint32_t accl[2][4][2],
    uint32_t a_hi, uint32_t a_lo, uint32_t b_hi,
    int m0, int n0, int lane)
{
    #pragma unroll
    for (int ks = 0; ks < 4; ks++) {
        const int bro = (n0 + (lane & 7)) * 128 + ks * 32 + ((lane >> 3) & 1) * 16;
        const int aro = (m0 + (lane & 15)) * 128 + ks * 32 + (lane >> 4) * 16;
        uint32_t bh[4][2];
        #pragma unroll
        for (int nt = 0; nt < 4; nt++)
            ldsm_x2(bh[nt], b_hi + SW(bro + nt * 1024));
        uint32_t ah[2][4], al[2][4];
        #pragma unroll
        for (int mt = 0; mt < 2; mt++) {
            ldsm_x4(ah[mt], a_hi + SW(aro + mt * 2048));
            ldsm_x4(al[mt], a_lo + SW(aro + mt * 2048));
        }
        #pragma unroll
        for (int mt = 0; mt < 2; mt++) {
            #pragma unroll
            for (int nt = 0; nt < 4; nt++) mma_f32(acc[mt][nt], ah[mt], bh[nt]);
            #pragma unroll
            for (int nt = 0; nt < 4; nt++) mma_f16(accl[mt][nt], al[mt], bh[nt]);
        }
    }
}

// ---------------- prep kernels ----------------
__global__ __launch_bounds__(256) void zero_border_kernel() {
    int idx = blockIdx.x * 256 + threadIdx.x;
    const int per_b = 516 * 32;
    if (idx >= B_ * per_b) return;
    int b = idx / per_b;
    int r = idx % per_b;
    int cell = r >> 5;
    int cgrp = r & 31;
    int y, x;
    if (cell < 130)      { y = 0;   x = cell; }
    else if (cell < 260) { y = 129; x = cell - 130; }
    else if (cell < 388) { y = 1 + (cell - 260); x = 0; }
    else                 { y = 1 + (cell - 388); x = 129; }
    size_t o = ((size_t)b * PADN + (size_t)y * PADW + x) * CIN + cgrp * 8;
    *(float4*)&g_fp_hi[o] = make_float4(0.f, 0.f, 0.f, 0.f);
    *(float4*)&g_fp_lo[o] = make_float4(0.f, 0.f, 0.f, 0.f);
}

__global__ __launch_bounds__(256) void transpose_cv(const float* __restrict__ feats) {
    __shared__ float s[32][33];
    int bid = blockIdx.x;
    int cblk = bid & 7;
    int xblk = (bid >> 3) & 3;
    int y    = (bid >> 5) & 127;
    int b    = bid >> 12;
    int c0 = cblk * 32, x0 = xblk * 32;
    int tid = threadIdx.x;

    #pragma unroll
    for (int r = 0; r < 4; r++) {
        int ci = (tid >> 5) + r * 8;
        int xi = tid & 31;
        s[ci][xi] = feats[(((size_t)b * CIN + c0 + ci) * Hdim + y) * Wdim + x0 + xi];
    }
    __syncthreads();
    #pragma unroll
    for (int r = 0; r < 4; r++) {
        int xj = (tid >> 5) + r * 8;
        int cj = tid & 31;
        float v = s[cj][xj];
        __half hi = __float2half(v);
        float lo = v - __half2float(hi);
        size_t idx = ((size_t)b * PADN + (size_t)(y + 1) * PADW + (x0 + xj + 1)) * CIN + c0 + cj;
        g_fp_hi[idx] = hi;
        g_fp_lo[idx] = __float2half(lo);
    }
}

__global__ __launch_bounds__(256) void prep_w2(const float* __restrict__ conv_w,
                                               const float* __restrict__ key_w,
                                               const float* __restrict__ query_w) {
    int i = blockIdx.x * 256 + threadIdx.x;
    if (i < 9 * KQ * CIN) {
        int t = i / (KQ * CIN);
        int rem = i % (KQ * CIN);
        int k = rem / CIN, c = rem % CIN;
        g_w_hi[i] = __float2half(conv_w[((size_t)k * CIN + c) * 9 + t]);
    }
    if (i < KQ * KQ) {
        g_kw_hi[i] = __float2half(key_w[i]);
        g_qw_hi[i] = __float2half(query_w[i]);
    }
}

// ---------------- fused conv3x3 + projections, 2-term fp16 split ----------------
// CTA = 512 threads (16 warps, 4x4 warp grid, warp tile M=32 x N=32), one (b, y).
// K = 9x256 in 36 chunks of 64; 3-stage (48KB) cp.async pipeline; x kept in SMEM.
__global__ __launch_bounds__(512, 1) void conv_fused(const float* __restrict__ conv_b,
                                                     const float* __restrict__ key_b,
                                                     const float* __restrict__ query_b) {
    extern __shared__ char smem[];
    const uint32_t sb0 = smem_u32(smem);
    const int tid = threadIdx.x, warp = tid >> 5, lane = tid & 31;
    const int y = blockIdx.x, bb = blockIdx.y;
    const int m0 = (warp & 3) * 32, n0 = (warp >> 2) * 32;

    float acc[2][4][4];
    uint32_t accl[2][4][2];
    #pragma unroll
    for (int mt = 0; mt < 2; mt++)
        #pragma unroll
        for (int nt = 0; nt < 4; nt++) {
            #pragma unroll
            for (int e = 0; e < 4; e++) acc[mt][nt][e] = 0.f;
            accl[mt][nt][0] = 0u; accl[mt][nt][1] = 0u;
        }

    const size_t apb = (size_t)bb * PADN;

    #pragma unroll 1
    for (int nid = 0; nid < 2; nid++) {
        int tap = nid >> 2, cc = nid & 3;
        int dy = tap / 3, dx = tap % 3;
        size_t arow = (apb + (size_t)(y + dy) * PADW + dx) * CIN + cc * 64;
        size_t wrow = (size_t)tap * KQ * CIN + cc * 64;
        stage_tiles(sb0 + (uint32_t)(nid % 3) * 49152u,
                    g_fp_hi + arow, g_fp_lo + arow, g_w_hi + wrow, CIN, CIN, tid);
        CP_COMMIT();
    }

    #pragma unroll 1
    for (int idx = 0; idx < 36; idx++) {
        CP_WAIT(1);
        __syncthreads();
        int nid = idx + 2;
        if (nid < 36) {
            int tap = nid >> 2, cc = nid & 3;
            int dy = tap / 3, dx = tap % 3;
            size_t arow = (apb + (size_t)(y + dy) * PADW + dx) * CIN + cc * 64;
            size_t wrow = (size_t)tap * KQ * CIN + cc * 64;
            stage_tiles(sb0 + (uint32_t)(nid % 3) * 49152u,
                        g_fp_hi + arow, g_fp_lo + arow, g_w_hi + wrow, CIN, CIN, tid);
        }
        CP_COMMIT();
        uint32_t tb = sb0 + (uint32_t)(idx % 3) * 49152u;
        compute_tile2(acc, accl, tb, tb + 16384, tb + 32768, m0, n0, lane);
    }
    __syncthreads();   // all compute done; stage buffers free

    // ---- issue proj-weight loads: kw_hi (2 cc tiles) @64K, qw_hi @96K ----
    // 4096 cp16 ops over 512 threads
    #pragma unroll
    for (int s = 0; s < 8; s++) {
        int i = tid + s * 512;
        int tile = i >> 10, j = i & 1023, r = j >> 3, c16 = j & 7;
        int tg = tile >> 1, cc = tile & 1;
        const __half* src = (tg ? g_qw_hi : g_kw_hi) + (size_t)r * KQ + cc * 64 + c16 * 8;
        cp16(sb0 + 65536u + tile * 16384 + SW(r * 128 + c16 * 16), src);
    }
    CP_COMMIT();

    // ---- conv epilogue: combine accs, bias, fp16 hi/lo split into [0,64K) ----
    // x_hi cc0 @0, x_hi cc1 @16K, x_lo cc0 @32K, x_lo cc1 @48K
    #pragma unroll
    for (int mt = 0; mt < 2; mt++) {
        #pragma unroll
        for (int nt = 0; nt < 4; nt++) {
            int n = n0 + nt * 8 + (lane & 3) * 2;
            float b0v = conv_b[n], b1v = conv_b[n + 1];
            uint32_t tbase = (uint32_t)((n >> 6) * 16384);
            #pragma unroll
            for (int half = 0; half < 2; half++) {
                int mrow = m0 + mt * 16 + (lane >> 2) + half * 8;
                float v0 = acc[mt][nt][half * 2 + 0] + lo_half(accl[mt][nt][half]) + b0v;
                float v1 = acc[mt][nt][half * 2 + 1] + hi_half(accl[mt][nt][half]) + b1v;
                __half h0 = __float2half(v0), h1 = __float2half(v1);
                float l0 = v0 - __half2float(h0);
                float l1 = v1 - __half2float(h1);
                uint32_t off = SW(mrow * 128 + (n & 63) * 2);
                *(uint32_t*)(smem + tbase + off)          = pack2h(h0, h1);
                *(uint32_t*)(smem + 32768 + tbase + off)  =
                    pack2h(__float2half(l0), __float2half(l1));
            }
        }
    }
    CP_WAIT(0);
    __syncthreads();

    // ---- projections: out[m][k] = sum_c x[m][c] * w[k][c] + bias ----
    const size_t mg = (size_t)bb * HW + (size_t)y * Wdim;
    #pragma unroll 1
    for (int tg = 0; tg < 2; tg++) {
        #pragma unroll
        for (int mt = 0; mt < 2; mt++)
            #pragma unroll
            for (int nt = 0; nt < 4; nt++) {
                #pragma unroll
                for (int e = 0; e < 4; e++) acc[mt][nt][e] = 0.f;
                accl[mt][nt][0] = 0u; accl[mt][nt][1] = 0u;
            }

        uint32_t wbase = sb0 + 65536u + (uint32_t)tg * 32768u;
        #pragma unroll
        for (int cc = 0; cc < 2; cc++) {
            compute_tile2(acc, accl,
                          sb0 + cc * 16384u, sb0 + 32768u + cc * 16384u,
                          wbase + cc * 16384u,
                          m0, n0, lane);
        }

        const float* bias = tg ? query_b : key_b;
        #pragma unroll
        for (int mt = 0; mt < 2; mt++) {
            #pragma unroll
            for (int nt = 0; nt < 4; nt++) {
                int n = n0 + nt * 8 + (lane & 3) * 2;
                float b0v = bias[n], b1v = bias[n + 1];
                #pragma unroll
                for (int half = 0; half < 2; half++) {
                    int mrow = m0 + mt * 16 + (lane >> 2) + half * 8;
                    float v0 = acc[mt][nt][half * 2 + 0] + lo_half(accl[mt][nt][half]) + b0v;
                    float v1 = acc[mt][nt][half * 2 + 1] + hi_half(accl[mt][nt][half]) + b1v;
                    size_t o = (mg + mrow) * KQ + n;
                    if (tg) {
                        *(float2*)&g_qrs[o] = make_float2(v0, v1);
                    } else {
                        *(uint32_t*)&g_keys_h[o] = pack2h(__float2half(v0), __float2half(v1));
                    }
                }
            }
        }
    }
}

// ---------------- avg pool (queries, fp32) ----------------
__global__ __launch_bounds__(256) void pool_q(int s) {
    const float* in = g_qrs;
    float* out = (s == 2) ? g_q2 : g_q4;
    const int hp = Hdim / s;
    const int n  = hp * hp;

    int idx = blockIdx.x * 256 + threadIdx.x;
    if (idx >= B_ * n * 32) return;
    int c4 = idx & 31;
    int nn = (idx >> 5) % n;
    int b  = idx / (n * 32);
    int yy = nn / hp, xx = nn % hp;

    float4 acc = make_float4(0.f, 0.f, 0.f, 0.f);
    for (int ry = 0; ry < s; ry++)
        for (int rx = 0; rx < s; rx++) {
            int m = (yy * s + ry) * Wdim + xx * s + rx;
            float4 v = *(const float4*)&in[((size_t)b * HW + m) * KQ + c4 * 4];
            acc.x += v.x; acc.y += v.y; acc.z += v.z; acc.w += v.w;
        }
    float inv = 1.f / (float)(s * s);
    acc.x *= inv; acc.y *= inv; acc.z *= inv; acc.w *= inv;
    *(float4*)&out[((size_t)b * n + nn) * KQ + c4 * 4] = acc;
}

// ---------------- avg pool (keys, fp16 in/out, fp32 accumulate) ----------------
__global__ __launch_bounds__(256) void pool_k(int s) {
    const __half* in = g_keys_h;
    __half* out = (s == 2) ? g_k2_h : g_k4_h;
    const int hp = Hdim / s;
    const int n  = hp * hp;

    int idx = blockIdx.x * 256 + threadIdx.x;
    if (idx >= B_ * n * 32) return;
    int c4 = idx & 31;
    int nn = (idx >> 5) % n;
    int b  = idx / (n * 32);
    int yy = nn / hp, xx = nn % hp;

    float acc0 = 0.f, acc1 = 0.f, acc2 = 0.f, acc3 = 0.f;
    for (int ry = 0; ry < s; ry++)
        for (int rx = 0; rx < s; rx++) {
            int m = (yy * s + ry) * Wdim + xx * s + rx;
            uint2 v = *(const uint2*)&in[((size_t)b * HW + m) * KQ + c4 * 4];
            acc0 += lo_half(v.x); acc1 += hi_half(v.x);
            acc2 += lo_half(v.y); acc3 += hi_half(v.y);
        }
    float inv = 1.f / (float)(s * s);
    uint2 r;
    r.x = pack2h(__float2half(acc0 * inv), __float2half(acc1 * inv));
    r.y = pack2h(__float2half(acc2 * inv), __float2half(acc3 * inv));
    *(uint2*)&out[((size_t)b * n + nn) * KQ + c4 * 4] = r;
}

// ---------------- logits: q fp32, k fp16 gather ----------------
__global__ __launch_bounds__(256) void logits_kernel(const int* __restrict__ inds,
                                                     float* __restrict__ out,
                                                     int n, int n_off, int lvl) {
    const float* q;
    const __half* k;
    if (lvl == 0)      { q = g_qrs; k = g_keys_h; }
    else if (lvl == 1) { q = g_q2;  k = g_k2_h;  }
    else               { q = g_q4;  k = g_k4_h;  }

    const int warp = threadIdx.x >> 5;
    const int lane = threadIdx.x & 31;
    const int nn = blockIdx.x * 8 + warp;
    const int b  = blockIdx.z;
    if (nn >= n) return;

    float4 qv = *(const float4*)&q[((size_t)b * n + nn) * KQ + lane * 4];
    const int* ip = inds + ((size_t)b * n + nn) * 32;

    float myval = 0.f;
    #pragma unroll 4
    for (int s = 0; s < 32; s++) {
        int ind = ip[s];
        uint2 kv = *(const uint2*)&k[((size_t)b * n + ind) * KQ + lane * 4];
        float p = qv.x * lo_half(kv.x) + qv.y * hi_half(kv.x)
                + qv.z * lo_half(kv.y) + qv.w * hi_half(kv.y);
        p += __shfl_xor_sync(0xffffffffu, p, 1);
        p += __shfl_xor_sync(0xffffffffu, p, 2);
        p += __shfl_xor_sync(0xffffffffu, p, 4);
        p += __shfl_xor_sync(0xffffffffu, p, 8);
        p += __shfl_xor_sync(0xffffffffu, p, 16);
        if (lane == s) myval = p * SCALE;
    }
    out[((size_t)b * NTOT + n_off + nn) * 32 + lane] = myval;
}

// ---------------- launch ----------------
extern "C" void kernel_launch(void* const* d_in, const int* in_sizes, int n_in,
                              void* d_out, int out_size) {
    const float* feats   = (const float*)d_in[0];
    const float* conv_w  = (const float*)d_in[1];
    const float* conv_b  = (const float*)d_in[2];
    const float* key_w   = (const float*)d_in[3];
    const float* key_b   = (const float*)d_in[4];
    const float* query_w = (const float*)d_in[5];
    const float* query_b = (const float*)d_in[6];
    const int* si2 = (const int*)d_in[7];
    const int* si3 = (const int*)d_in[8];
    const int* si4 = (const int*)d_in[9];
    float* out = (float*)d_out;

    static bool attr_set = false;
    if (!attr_set) {
        cudaFuncSetAttribute(conv_fused, cudaFuncAttributeMaxDynamicSharedMemorySize, SMEM_BYTES);
        attr_set = true;
    }

    zero_border_kernel<<<(B_ * 516 * 32 + 255) / 256, 256>>>();
    transpose_cv<<<8192, 256>>>(feats);
    prep_w2<<<(9 * KQ * CIN + 255) / 256, 256>>>(conv_w, key_w, query_w);
    conv_fused<<<dim3(Hdim, B_), 512, SMEM_BYTES>>>(conv_b, key_b, query_b);
    pool_q<<<(B_ * 4096 * 32 + 255) / 256, 256>>>(2);
    pool_q<<<(B_ * 1024 * 32 + 255) / 256, 256>>>(4);
    pool_k<<<(B_ * 4096 * 32 + 255) / 256, 256>>>(2);
    pool_k<<<(B_ * 1024 * 32 + 255) / 256, 256>>>(4);
    logits_kernel<<<dim3(16384 / 8, 1, B_), 256>>>(si2, out, 16384, 0, 0);
    logits_kernel<<<dim3(4096 / 8, 1, B_), 256>>>(si3, out, 4096, 16384, 1);
    logits_kernel<<<dim3(1024 / 8, 1, B_), 256>>>(si4, out, 1024, 20480, 2);
}

// round 14
// speedup vs baseline: 1.1254x; 1.1254x over previous
#include <cuda_runtime.h>
#include <cuda_fp16.h>
#include <cstdint>

#define B_      2
#define CIN     256
#define Hdim    128
#define Wdim    128
#define KQ      128
#define HW      16384
#define NTOT    21504   // 16384 + 4096 + 1024
#define SCALE   0.08838834764831845f
#define PADW    130
#define PADN    16900   // 130*130

#define SMEM_BYTES 147456   // 3 stages x 48KB
#define SW(o) ((uint32_t)(o) ^ ((((uint32_t)(o)) >> 3) & 0x70u))

// ---------------- device scratch ----------------
__device__ __half g_fp_hi[B_ * PADN * CIN];
__device__ __half g_fp_lo[B_ * PADN * CIN];
__device__ __half g_w_hi[9 * KQ * CIN];
__device__ __half g_kw_hi[KQ * KQ];
__device__ __half g_qw_hi[KQ * KQ];
__device__ __half g_keys_h[B_ * HW * KQ];          // keys fp16 (gathered by logits)
__device__ float  g_qrs[B_ * HW * KQ];             // queries fp32
__device__ __half g_k2_h[B_ * 4096 * KQ], g_k4_h[B_ * 1024 * KQ];
__device__ float  g_q2[B_ * 4096 * KQ],  g_q4[B_ * 1024 * KQ];

// ---------------- helpers ----------------
__device__ __forceinline__ uint32_t smem_u32(const void* p) {
    uint32_t a;
    asm("{ .reg .u64 t; cvta.to.shared.u64 t, %1; cvt.u32.u64 %0, t; }" : "=r"(a) : "l"(p));
    return a;
}
__device__ __forceinline__ void cp16(uint32_t dst, const void* src) {
    asm volatile("cp.async.cg.shared.global [%0], [%1], 16;" :: "r"(dst), "l"(src) : "memory");
}
#define CP_COMMIT() asm volatile("cp.async.commit_group;" ::: "memory")
#define CP_WAIT(n)  asm volatile("cp.async.wait_group %0;" :: "n"(n) : "memory")

__device__ __forceinline__ void ldsm_x4(uint32_t* r, uint32_t addr) {
    asm volatile("ldmatrix.sync.aligned.m8n8.x4.shared.b16 {%0,%1,%2,%3}, [%4];"
                 : "=r"(r[0]), "=r"(r[1]), "=r"(r[2]), "=r"(r[3]) : "r"(addr));
}
__device__ __forceinline__ void ldsm_x2(uint32_t* r, uint32_t addr) {
    asm volatile("ldmatrix.sync.aligned.m8n8.x2.shared.b16 {%0,%1}, [%2];"
                 : "=r"(r[0]), "=r"(r[1]) : "r"(addr));
}
// fp16 inputs, fp32 accumulator
__device__ __forceinline__ void mma_f32(float* c, const uint32_t* a, const uint32_t* b) {
    asm volatile("mma.sync.aligned.m16n8k16.row.col.f32.f16.f16.f32 "
                 "{%0,%1,%2,%3}, {%4,%5,%6,%7}, {%8,%9}, {%0,%1,%2,%3};"
                 : "+f"(c[0]), "+f"(c[1]), "+f"(c[2]), "+f"(c[3])
                 : "r"(a[0]), "r"(a[1]), "r"(a[2]), "r"(a[3]), "r"(b[0]), "r"(b[1]));
}
// fp16 inputs, fp16 accumulator (low-order term; magnitudes tiny)
__device__ __forceinline__ void mma_f16(uint32_t* c, const uint32_t* a, const uint32_t* b) {
    asm volatile("mma.sync.aligned.m16n8k16.row.col.f16.f16.f16.f16 "
                 "{%0,%1}, {%2,%3,%4,%5}, {%6,%7}, {%0,%1};"
                 : "+r"(c[0]), "+r"(c[1])
                 : "r"(a[0]), "r"(a[1]), "r"(a[2]), "r"(a[3]), "r"(b[0]), "r"(b[1]));
}
__device__ __forceinline__ uint32_t pack2h(__half a, __half b) {
    return (uint32_t)__half_as_ushort(a) | ((uint32_t)__half_as_ushort(b) << 16);
}
__device__ __forceinline__ float lo_half(uint32_t r) {
    return __half2float(__ushort_as_half((unsigned short)(r & 0xffffu)));
}
__device__ __forceinline__ float hi_half(uint32_t r) {
    return __half2float(__ushort_as_half((unsigned short)(r >> 16)));
}

// Stage 3 tiles (A_hi, A_lo, B_hi), each [128 rows x 64 fp16] SW128-swizzled. 48KB.
__device__ __forceinline__ void stage_tiles(uint32_t sdst,
    const __half* a_hi, const __half* a_lo, const __half* b_hi,
    int a_stride, int b_stride, int tid)
{
    #pragma unroll
    for (int s = 0; s < 12; s++) {
        int i = tid + s * 256;
        int tile = i >> 10, j = i & 1023, r = j >> 3, c16 = j & 7;
        const __half* src;
        if (tile == 0)      src = a_hi + (size_t)r * a_stride;
        else if (tile == 1) src = a_lo + (size_t)r * a_stride;
        else                src = b_hi + (size_t)r * b_stride;
        cp16(sdst + tile * 16384 + SW(r * 128 + c16 * 16), src + c16 * 8);
    }
}

// One 128x128x64 split-GEMM step: ah*bh (f32 acc) + al*bh (f16 acc).
__device__ __forceinline__ void compute_tile2(float acc[2][8][4], uint32_t accl[2][8][2],
    uint32_t a_hi, uint32_t a_lo, uint32_t b_hi,
    int m0, int n0, int lane)
{
    #pragma unroll
    for (int ks = 0; ks < 4; ks++) {
        const int bro = (n0 + (lane & 7)) * 128 + ks * 32 + ((lane >> 3) & 1) * 16;
        const int aro = (m0 + (lane & 15)) * 128 + ks * 32 + (lane >> 4) * 16;
        uint32_t bh[8][2];
        #pragma unroll
        for (int nt = 0; nt < 8; nt++)
            ldsm_x2(bh[nt], b_hi + SW(bro + nt * 1024));
        uint32_t ah[2][4], al[2][4];
        #pragma unroll
        for (int mt = 0; mt < 2; mt++) {
            ldsm_x4(ah[mt], a_hi + SW(aro + mt * 2048));
            ldsm_x4(al[mt], a_lo + SW(aro + mt * 2048));
        }
        #pragma unroll
        for (int mt = 0; mt < 2; mt++) {
            #pragma unroll
            for (int nt = 0; nt < 8; nt++) mma_f32(acc[mt][nt], ah[mt], bh[nt]);
            #pragma unroll
            for (int nt = 0; nt < 8; nt++) mma_f16(accl[mt][nt], al[mt], bh[nt]);
        }
    }
}

// ---------------- prep kernels ----------------
__global__ __launch_bounds__(256) void zero_border_kernel() {
    int idx = blockIdx.x * 256 + threadIdx.x;
    const int per_b = 516 * 32;
    if (idx >= B_ * per_b) return;
    int b = idx / per_b;
    int r = idx % per_b;
    int cell = r >> 5;
    int cgrp = r & 31;
    int y, x;
    if (cell < 130)      { y = 0;   x = cell; }
    else if (cell < 260) { y = 129; x = cell - 130; }
    else if (cell < 388) { y = 1 + (cell - 260); x = 0; }
    else                 { y = 1 + (cell - 388); x = 129; }
    size_t o = ((size_t)b * PADN + (size_t)y * PADW + x) * CIN + cgrp * 8;
    *(float4*)&g_fp_hi[o] = make_float4(0.f, 0.f, 0.f, 0.f);
    *(float4*)&g_fp_lo[o] = make_float4(0.f, 0.f, 0.f, 0.f);
}

__global__ __launch_bounds__(256) void transpose_cv(const float* __restrict__ feats) {
    __shared__ float s[32][33];
    int bid = blockIdx.x;
    int cblk = bid & 7;
    int xblk = (bid >> 3) & 3;
    int y    = (bid >> 5) & 127;
    int b    = bid >> 12;
    int c0 = cblk * 32, x0 = xblk * 32;
    int tid = threadIdx.x;

    #pragma unroll
    for (int r = 0; r < 4; r++) {
        int ci = (tid >> 5) + r * 8;
        int xi = tid & 31;
        s[ci][xi] = feats[(((size_t)b * CIN + c0 + ci) * Hdim + y) * Wdim + x0 + xi];
    }
    __syncthreads();
    #pragma unroll
    for (int r = 0; r < 4; r++) {
        int xj = (tid >> 5) + r * 8;
        int cj = tid & 31;
        float v = s[cj][xj];
        __half hi = __float2half(v);
        float lo = v - __half2float(hi);
        size_t idx = ((size_t)b * PADN + (size_t)(y + 1) * PADW + (x0 + xj + 1)) * CIN + c0 + cj;
        g_fp_hi[idx] = hi;
        g_fp_lo[idx] = __float2half(lo);
    }
}

__global__ __launch_bounds__(256) void prep_w2(const float* __restrict__ conv_w,
                                               const float* __restrict__ key_w,
                                               const float* __restrict__ query_w) {
    int i = blockIdx.x * 256 + threadIdx.x;
    if (i < 9 * KQ * CIN) {
        int t = i / (KQ * CIN);
        int rem = i % (KQ * CIN);
        int k = rem / CIN, c = rem % CIN;
        g_w_hi[i] = __float2half(conv_w[((size_t)k * CIN + c) * 9 + t]);
    }
    if (i < KQ * KQ) {
        g_kw_hi[i] = __float2half(key_w[i]);
        g_qw_hi[i] = __float2half(query_w[i]);
    }
}

// ---------------- fused conv3x3 + projections, 2-term fp16 split ----------------
// CTA = 256 threads, one (b, y). K = 9x256 in 36 chunks of 64; 3-stage pipeline.
__global__ __launch_bounds__(256, 1) void conv_fused(const float* __restrict__ conv_b,
                                                     const float* __restrict__ key_b,
                                                     const float* __restrict__ query_b) {
    extern __shared__ char smem[];
    const uint32_t sb0 = smem_u32(smem);
    const int tid = threadIdx.x, warp = tid >> 5, lane = tid & 31;
    const int y = blockIdx.x, bb = blockIdx.y;
    const int m0 = (warp & 3) * 32, n0 = (warp >> 2) * 64;

    float acc[2][8][4];
    uint32_t accl[2][8][2];
    #pragma unroll
    for (int mt = 0; mt < 2; mt++)
        #pragma unroll
        for (int nt = 0; nt < 8; nt++) {
            #pragma unroll
            for (int e = 0; e < 4; e++) acc[mt][nt][e] = 0.f;
            accl[mt][nt][0] = 0u; accl[mt][nt][1] = 0u;
        }

    const size_t apb = (size_t)bb * PADN;

    #pragma unroll 1
    for (int nid = 0; nid < 2; nid++) {
        int tap = nid >> 2, cc = nid & 3;
        int dy = tap / 3, dx = tap % 3;
        size_t arow = (apb + (size_t)(y + dy) * PADW + dx) * CIN + cc * 64;
        size_t wrow = (size_t)tap * KQ * CIN + cc * 64;
        stage_tiles(sb0 + (uint32_t)(nid % 3) * 49152u,
                    g_fp_hi + arow, g_fp_lo + arow, g_w_hi + wrow, CIN, CIN, tid);
        CP_COMMIT();
    }

    #pragma unroll 1
    for (int idx = 0; idx < 36; idx++) {
        CP_WAIT(1);
        __syncthreads();
        int nid = idx + 2;
        if (nid < 36) {
            int tap = nid >> 2, cc = nid & 3;
            int dy = tap / 3, dx = tap % 3;
            size_t arow = (apb + (size_t)(y + dy) * PADW + dx) * CIN + cc * 64;
            size_t wrow = (size_t)tap * KQ * CIN + cc * 64;
            stage_tiles(sb0 + (uint32_t)(nid % 3) * 49152u,
                        g_fp_hi + arow, g_fp_lo + arow, g_w_hi + wrow, CIN, CIN, tid);
        }
        CP_COMMIT();
        uint32_t tb = sb0 + (uint32_t)(idx % 3) * 49152u;
        compute_tile2(acc, accl, tb, tb + 16384, tb + 32768, m0, n0, lane);
    }
    __syncthreads();   // all compute done; stage buffers free

    // ---- issue proj-weight loads: kw_hi (2 cc tiles) @64K, qw_hi @96K ----
    #pragma unroll
    for (int s = 0; s < 16; s++) {
        int i = tid + s * 256;
        int tile = i >> 10, j = i & 1023, r = j >> 3, c16 = j & 7;
        int tg = tile >> 1, cc = tile & 1;
        const __half* src = (tg ? g_qw_hi : g_kw_hi) + (size_t)r * KQ + cc * 64 + c16 * 8;
        cp16(sb0 + 65536u + tile * 16384 + SW(r * 128 + c16 * 16), src);
    }
    CP_COMMIT();

    // ---- conv epilogue: combine accs, bias, fp16 hi/lo split into [0,64K) ----
    #pragma unroll
    for (int mt = 0; mt < 2; mt++) {
        #pragma unroll
        for (int nt = 0; nt < 8; nt++) {
            int n = n0 + nt * 8 + (lane & 3) * 2;
            float b0v = conv_b[n], b1v = conv_b[n + 1];
            uint32_t tbase = (uint32_t)((n >> 6) * 16384);
            #pragma unroll
            for (int half = 0; half < 2; half++) {
                int mrow = m0 + mt * 16 + (lane >> 2) + half * 8;
                float v0 = acc[mt][nt][half * 2 + 0] + lo_half(accl[mt][nt][half]) + b0v;
                float v1 = acc[mt][nt][half * 2 + 1] + hi_half(accl[mt][nt][half]) + b1v;
                __half h0 = __float2half(v0), h1 = __float2half(v1);
                float l0 = v0 - __half2float(h0);
                float l1 = v1 - __half2float(h1);
                uint32_t off = SW(mrow * 128 + (n & 63) * 2);
                *(uint32_t*)(smem + tbase + off)          = pack2h(h0, h1);
                *(uint32_t*)(smem + 32768 + tbase + off)  =
                    pack2h(__float2half(l0), __float2half(l1));
            }
        }
    }
    CP_WAIT(0);
    __syncthreads();

    // ---- projections: out[m][k] = sum_c x[m][c] * w[k][c] + bias ----
    const size_t mg = (size_t)bb * HW + (size_t)y * Wdim;
    #pragma unroll 1
    for (int tg = 0; tg < 2; tg++) {
        #pragma unroll
        for (int mt = 0; mt < 2; mt++)
            #pragma unroll
            for (int nt = 0; nt < 8; nt++) {
                #pragma unroll
                for (int e = 0; e < 4; e++) acc[mt][nt][e] = 0.f;
                accl[mt][nt][0] = 0u; accl[mt][nt][1] = 0u;
            }

        uint32_t wbase = sb0 + 65536u + (uint32_t)tg * 32768u;
        #pragma unroll
        for (int cc = 0; cc < 2; cc++) {
            compute_tile2(acc, accl,
                          sb0 + cc * 16384u, sb0 + 32768u + cc * 16384u,
                          wbase + cc * 16384u,
                          m0, n0, lane);
        }

        const float* bias = tg ? query_b : key_b;
        #pragma unroll
        for (int mt = 0; mt < 2; mt++) {
            #pragma unroll
            for (int nt = 0; nt < 8; nt++) {
                int n = n0 + nt * 8 + (lane & 3) * 2;
                float b0v = bias[n], b1v = bias[n + 1];
                #pragma unroll
                for (int half = 0; half < 2; half++) {
                    int mrow = m0 + mt * 16 + (lane >> 2) + half * 8;
                    float v0 = acc[mt][nt][half * 2 + 0] + lo_half(accl[mt][nt][half]) + b0v;
                    float v1 = acc[mt][nt][half * 2 + 1] + hi_half(accl[mt][nt][half]) + b1v;
                    size_t o = (mg + mrow) * KQ + n;
                    if (tg) {
                        *(float2*)&g_qrs[o] = make_float2(v0, v1);
                    } else {
                        *(uint32_t*)&g_keys_h[o] = pack2h(__float2half(v0), __float2half(v1));
                    }
                }
            }
        }
    }
}

// ---------------- combined avg pool: z=0 queries(fp32), z=1 keys(fp16) ----------------
// x-range: [0, 262144) -> s=2 ; [262144, 327680) -> s=4   (thread-granular)
__global__ __launch_bounds__(256) void pool_all() {
    int idx = blockIdx.x * 256 + threadIdx.x;
    int s, base;
    if (idx < B_ * 4096 * 32) { s = 2; base = 0; }
    else { s = 4; base = B_ * 4096 * 32; idx -= base; if (idx >= B_ * 1024 * 32) return; }
    const int hp = Hdim / s;
    const int n  = hp * hp;
    int c4 = idx & 31;
    int nn = (idx >> 5) % n;
    int b  = idx / (n * 32);
    int yy = nn / hp, xx = nn % hp;

    if (blockIdx.z == 0) {
        const float* in = g_qrs;
        float* out = (s == 2) ? g_q2 : g_q4;
        float4 acc = make_float4(0.f, 0.f, 0.f, 0.f);
        for (int ry = 0; ry < s; ry++)
            for (int rx = 0; rx < s; rx++) {
                int m = (yy * s + ry) * Wdim + xx * s + rx;
                float4 v = *(const float4*)&in[((size_t)b * HW + m) * KQ + c4 * 4];
                acc.x += v.x; acc.y += v.y; acc.z += v.z; acc.w += v.w;
            }
        float inv = 1.f / (float)(s * s);
        acc.x *= inv; acc.y *= inv; acc.z *= inv; acc.w *= inv;
        *(float4*)&out[((size_t)b * n + nn) * KQ + c4 * 4] = acc;
    } else {
        const __half* in = g_keys_h;
        __half* out = (s == 2) ? g_k2_h : g_k4_h;
        float a0 = 0.f, a1 = 0.f, a2 = 0.f, a3 = 0.f;
        for (int ry = 0; ry < s; ry++)
            for (int rx = 0; rx < s; rx++) {
                int m = (yy * s + ry) * Wdim + xx * s + rx;
                uint2 v = *(const uint2*)&in[((size_t)b * HW + m) * KQ + c4 * 4];
                a0 += lo_half(v.x); a1 += hi_half(v.x);
                a2 += lo_half(v.y); a3 += hi_half(v.y);
            }
        float inv = 1.f / (float)(s * s);
        uint2 r;
        r.x = pack2h(__float2half(a0 * inv), __float2half(a1 * inv));
        r.y = pack2h(__float2half(a2 * inv), __float2half(a3 * inv));
        *(uint2*)&out[((size_t)b * n + nn) * KQ + c4 * 4] = r;
    }
}

// ---------------- logits: all levels, MLP=32 gather ----------------
// blockIdx.x: [0,2048) lvl0, [2048,2560) lvl1, [2560,2688) lvl2. 8 positions/CTA.
__global__ __launch_bounds__(256) void logits_all(const int* __restrict__ si2,
                                                  const int* __restrict__ si3,
                                                  const int* __restrict__ si4,
                                                  float* __restrict__ out) {
    int bx = blockIdx.x;
    const float* q;
    const __half* k;
    const int* inds;
    int n, n_off, lbase;
    if (bx < 2048)      { q = g_qrs; k = g_keys_h; inds = si2; n = 16384; n_off = 0;     lbase = bx; }
    else if (bx < 2560) { q = g_q2;  k = g_k2_h;   inds = si3; n = 4096;  n_off = 16384; lbase = bx - 2048; }
    else                { q = g_q4;  k = g_k4_h;   inds = si4; n = 1024;  n_off = 20480; lbase = bx - 2560; }

    const int warp = threadIdx.x >> 5;
    const int lane = threadIdx.x & 31;
    const int nn = lbase * 8 + warp;
    const int b  = blockIdx.z;

    float4 qv = *(const float4*)&q[((size_t)b * n + nn) * KQ + lane * 4];
    // coalesced index preload: lane l holds index of sample l
    int myind = inds[((size_t)b * n + nn) * 32 + lane];

    const __half* kb = k + (size_t)b * n * KQ;
    // issue all 32 gathers up front (MLP = 32)
    uint2 kv[32];
    #pragma unroll
    for (int s = 0; s < 32; s++) {
        int ind = __shfl_sync(0xffffffffu, myind, s);
        kv[s] = *(const uint2*)&kb[(size_t)ind * KQ + lane * 4];
    }

    float myval = 0.f;
    #pragma unroll
    for (int s = 0; s < 32; s++) {
        float p = qv.x * lo_half(kv[s].x) + qv.y * hi_half(kv[s].x)
                + qv.z * lo_half(kv[s].y) + qv.w * hi_half(kv[s].y);
        p += __shfl_xor_sync(0xffffffffu, p, 1);
        p += __shfl_xor_sync(0xffffffffu, p, 2);
        p += __shfl_xor_sync(0xffffffffu, p, 4);
        p += __shfl_xor_sync(0xffffffffu, p, 8);
        p += __shfl_xor_sync(0xffffffffu, p, 16);
        if (lane == s) myval = p * SCALE;
    }
    out[((size_t)b * NTOT + n_off + nn) * 32 + lane] = myval;
}

// ---------------- launch ----------------
extern "C" void kernel_launch(void* const* d_in, const int* in_sizes, int n_in,
                              void* d_out, int out_size) {
    const float* feats   = (const float*)d_in[0];
    const float* conv_w  = (const float*)d_in[1];
    const float* conv_b  = (const float*)d_in[2];
    const float* key_w   = (const float*)d_in[3];
    const float* key_b   = (const float*)d_in[4];
    const float* query_w = (const float*)d_in[5];
    const float* query_b = (const float*)d_in[6];
    const int* si2 = (const int*)d_in[7];
    const int* si3 = (const int*)d_in[8];
    const int* si4 = (const int*)d_in[9];
    float* out = (float*)d_out;

    static bool attr_set = false;
    if (!attr_set) {
        cudaFuncSetAttribute(conv_fused, cudaFuncAttributeMaxDynamicSharedMemorySize, SMEM_BYTES);
        attr_set = true;
    }

    zero_border_kernel<<<(B_ * 516 * 32 + 255) / 256, 256>>>();
    transpose_cv<<<8192, 256>>>(feats);
    prep_w2<<<(9 * KQ * CIN + 255) / 256, 256>>>(conv_w, key_w, query_w);
    conv_fused<<<dim3(Hdim, B_), 256, SMEM_BYTES>>>(conv_b, key_b, query_b);
    pool_all<<<dim3((B_ * (4096 + 1024) * 32 + 255) / 256, 1, 2), 256>>>();
    logits_all<<<dim3(2688, 1, B_), 256>>>(si2, si3, si4, out);
}

// round 15
// speedup vs baseline: 1.5335x; 1.3626x over previous
#include <cuda_runtime.h>
#include <cuda_fp16.h>
#include <cstdint>

#define B_      2
#define CIN     256
#define Hdim    128
#define Wdim    128
#define KQ      128
#define HW      16384
#define NTOT    21504   // 16384 + 4096 + 1024
#define SCALE   0.08838834764831845f
#define PADW    130
#define PADN    16900   // 130*130

#define SMEM_BYTES 98304   // 3 stages x 32KB
#define SW(o) ((uint32_t)(o) ^ ((((uint32_t)(o)) >> 3) & 0x70u))

// ---------------- device scratch ----------------
__device__ __half g_fp_hi[B_ * PADN * CIN];        // padded feats, fp16
__device__ __half g_w_hi[9 * KQ * CIN];
__device__ __half g_kw_hi[KQ * KQ];
__device__ __half g_qw_hi[KQ * KQ];
__device__ __half g_keys_h[B_ * HW * KQ];          // keys fp16 (gathered by logits)
__device__ float  g_qrs[B_ * HW * KQ];             // queries fp32
__device__ __half g_k2_h[B_ * 4096 * KQ], g_k4_h[B_ * 1024 * KQ];
__device__ float  g_q2[B_ * 4096 * KQ],  g_q4[B_ * 1024 * KQ];

// ---------------- helpers ----------------
__device__ __forceinline__ uint32_t smem_u32(const void* p) {
    uint32_t a;
    asm("{ .reg .u64 t; cvta.to.shared.u64 t, %1; cvt.u32.u64 %0, t; }" : "=r"(a) : "l"(p));
    return a;
}
__device__ __forceinline__ void cp16(uint32_t dst, const void* src) {
    asm volatile("cp.async.cg.shared.global [%0], [%1], 16;" :: "r"(dst), "l"(src) : "memory");
}
#define CP_COMMIT() asm volatile("cp.async.commit_group;" ::: "memory")
#define CP_WAIT(n)  asm volatile("cp.async.wait_group %0;" :: "n"(n) : "memory")

__device__ __forceinline__ void ldsm_x4(uint32_t* r, uint32_t addr) {
    asm volatile("ldmatrix.sync.aligned.m8n8.x4.shared.b16 {%0,%1,%2,%3}, [%4];"
                 : "=r"(r[0]), "=r"(r[1]), "=r"(r[2]), "=r"(r[3]) : "r"(addr));
}
__device__ __forceinline__ void ldsm_x2(uint32_t* r, uint32_t addr) {
    asm volatile("ldmatrix.sync.aligned.m8n8.x2.shared.b16 {%0,%1}, [%2];"
                 : "=r"(r[0]), "=r"(r[1]) : "r"(addr));
}
// fp16 inputs, fp32 accumulator
__device__ __forceinline__ void mma_f32(float* c, const uint32_t* a, const uint32_t* b) {
    asm volatile("mma.sync.aligned.m16n8k16.row.col.f32.f16.f16.f32 "
                 "{%0,%1,%2,%3}, {%4,%5,%6,%7}, {%8,%9}, {%0,%1,%2,%3};"
                 : "+f"(c[0]), "+f"(c[1]), "+f"(c[2]), "+f"(c[3])
                 : "r"(a[0]), "r"(a[1]), "r"(a[2]), "r"(a[3]), "r"(b[0]), "r"(b[1]));
}
__device__ __forceinline__ uint32_t pack2h(__half a, __half b) {
    return (uint32_t)__half_as_ushort(a) | ((uint32_t)__half_as_ushort(b) << 16);
}
__device__ __forceinline__ float lo_half(uint32_t r) {
    return __half2float(__ushort_as_half((unsigned short)(r & 0xffffu)));
}
__device__ __forceinline__ float hi_half(uint32_t r) {
    return __half2float(__ushort_as_half((unsigned short)(r >> 16)));
}

// Stage 2 tiles (A, B), each [128 rows x 64 fp16] SW128-swizzled. 32KB total.
__device__ __forceinline__ void stage_tiles(uint32_t sdst,
    const __half* a, const __half* b,
    int a_stride, int b_stride, int tid)
{
    #pragma unroll
    for (int s = 0; s < 8; s++) {
        int i = tid + s * 256;
        int tile = i >> 10, j = i & 1023, r = j >> 3, c16 = j & 7;
        const __half* src = tile ? (b + (size_t)r * b_stride) : (a + (size_t)r * a_stride);
        cp16(sdst + tile * 16384 + SW(r * 128 + c16 * 16), src + c16 * 8);
    }
}

// One 128x128x64 GEMM step, pure fp16 inputs, fp32 acc.
__device__ __forceinline__ void compute_tile1(float acc[2][8][4],
    uint32_t a_t, uint32_t b_t, int m0, int n0, int lane)
{
    #pragma unroll
    for (int ks = 0; ks < 4; ks++) {
        const int bro = (n0 + (lane & 7)) * 128 + ks * 32 + ((lane >> 3) & 1) * 16;
        const int aro = (m0 + (lane & 15)) * 128 + ks * 32 + (lane >> 4) * 16;
        uint32_t bh[8][2];
        #pragma unroll
        for (int nt = 0; nt < 8; nt++)
            ldsm_x2(bh[nt], b_t + SW(bro + nt * 1024));
        uint32_t ah[2][4];
        #pragma unroll
        for (int mt = 0; mt < 2; mt++)
            ldsm_x4(ah[mt], a_t + SW(aro + mt * 2048));
        #pragma unroll
        for (int mt = 0; mt < 2; mt++)
            #pragma unroll
            for (int nt = 0; nt < 8; nt++)
                mma_f32(acc[mt][nt], ah[mt], bh[nt]);
    }
}

// ---------------- prep kernels ----------------
__global__ __launch_bounds__(256) void zero_border_kernel() {
    int idx = blockIdx.x * 256 + threadIdx.x;
    const int per_b = 516 * 32;
    if (idx >= B_ * per_b) return;
    int b = idx / per_b;
    int r = idx % per_b;
    int cell = r >> 5;
    int cgrp = r & 31;
    int y, x;
    if (cell < 130)      { y = 0;   x = cell; }
    else if (cell < 260) { y = 129; x = cell - 130; }
    else if (cell < 388) { y = 1 + (cell - 260); x = 0; }
    else                 { y = 1 + (cell - 388); x = 129; }
    size_t o = ((size_t)b * PADN + (size_t)y * PADW + x) * CIN + cgrp * 8;
    *(float4*)&g_fp_hi[o] = make_float4(0.f, 0.f, 0.f, 0.f);
}

__global__ __launch_bounds__(256) void transpose_cv(const float* __restrict__ feats) {
    __shared__ float s[32][33];
    int bid = blockIdx.x;
    int cblk = bid & 7;
    int xblk = (bid >> 3) & 3;
    int y    = (bid >> 5) & 127;
    int b    = bid >> 12;
    int c0 = cblk * 32, x0 = xblk * 32;
    int tid = threadIdx.x;

    #pragma unroll
    for (int r = 0; r < 4; r++) {
        int ci = (tid >> 5) + r * 8;
        int xi = tid & 31;
        s[ci][xi] = feats[(((size_t)b * CIN + c0 + ci) * Hdim + y) * Wdim + x0 + xi];
    }
    __syncthreads();
    #pragma unroll
    for (int r = 0; r < 4; r++) {
        int xj = (tid >> 5) + r * 8;
        int cj = tid & 31;
        size_t idx = ((size_t)b * PADN + (size_t)(y + 1) * PADW + (x0 + xj + 1)) * CIN + c0 + cj;
        g_fp_hi[idx] = __float2half(s[cj][xj]);
    }
}

__global__ __launch_bounds__(256) void prep_w2(const float* __restrict__ conv_w,
                                               const float* __restrict__ key_w,
                                               const float* __restrict__ query_w) {
    int i = blockIdx.x * 256 + threadIdx.x;
    if (i < 9 * KQ * CIN) {
        int t = i / (KQ * CIN);
        int rem = i % (KQ * CIN);
        int k = rem / CIN, c = rem % CIN;
        g_w_hi[i] = __float2half(conv_w[((size_t)k * CIN + c) * 9 + t]);
    }
    if (i < KQ * KQ) {
        g_kw_hi[i] = __float2half(key_w[i]);
        g_qw_hi[i] = __float2half(query_w[i]);
    }
}

// ---------------- fused conv3x3 + projections, pure fp16 GEMM ----------------
// CTA = 256 threads, one (b, y). K = 9x256 in 36 chunks of 64; 3-stage (32KB)
// pipeline; 2 CTAs/SM (96KB smem, <=128 regs). x kept in SMEM for projections.
__global__ __launch_bounds__(256, 2) void conv_fused(const float* __restrict__ conv_b,
                                                     const float* __restrict__ key_b,
                                                     const float* __restrict__ query_b) {
    extern __shared__ char smem[];
    const uint32_t sb0 = smem_u32(smem);
    const int tid = threadIdx.x, warp = tid >> 5, lane = tid & 31;
    const int y = blockIdx.x, bb = blockIdx.y;
    const int m0 = (warp & 3) * 32, n0 = (warp >> 2) * 64;

    float acc[2][8][4];
    #pragma unroll
    for (int mt = 0; mt < 2; mt++)
        #pragma unroll
        for (int nt = 0; nt < 8; nt++)
            #pragma unroll
            for (int e = 0; e < 4; e++) acc[mt][nt][e] = 0.f;

    const size_t apb = (size_t)bb * PADN;

    #pragma unroll 1
    for (int nid = 0; nid < 2; nid++) {
        int tap = nid >> 2, cc = nid & 3;
        int dy = tap / 3, dx = tap % 3;
        size_t arow = (apb + (size_t)(y + dy) * PADW + dx) * CIN + cc * 64;
        size_t wrow = (size_t)tap * KQ * CIN + cc * 64;
        stage_tiles(sb0 + (uint32_t)(nid % 3) * 32768u,
                    g_fp_hi + arow, g_w_hi + wrow, CIN, CIN, tid);
        CP_COMMIT();
    }

    #pragma unroll 1
    for (int idx = 0; idx < 36; idx++) {
        CP_WAIT(1);
        __syncthreads();
        int nid = idx + 2;
        if (nid < 36) {
            int tap = nid >> 2, cc = nid & 3;
            int dy = tap / 3, dx = tap % 3;
            size_t arow = (apb + (size_t)(y + dy) * PADW + dx) * CIN + cc * 64;
            size_t wrow = (size_t)tap * KQ * CIN + cc * 64;
            stage_tiles(sb0 + (uint32_t)(nid % 3) * 32768u,
                        g_fp_hi + arow, g_w_hi + wrow, CIN, CIN, tid);
        }
        CP_COMMIT();
        uint32_t tb = sb0 + (uint32_t)(idx % 3) * 32768u;
        compute_tile1(acc, tb, tb + 16384, m0, n0, lane);
    }
    __syncthreads();   // all compute done; stage buffers free

    // ---- issue proj-weight loads: kw @[32K,64K), qw @[64K,96K) (2 cc tiles each) ----
    #pragma unroll
    for (int s = 0; s < 16; s++) {
        int i = tid + s * 256;
        int tile = i >> 10, j = i & 1023, r = j >> 3, c16 = j & 7;
        int tg = tile >> 1, cc = tile & 1;
        const __half* src = (tg ? g_qw_hi : g_kw_hi) + (size_t)r * KQ + cc * 64 + c16 * 8;
        cp16(sb0 + 32768u + tile * 16384u + SW(r * 128 + c16 * 16), src);
    }
    CP_COMMIT();

    // ---- conv epilogue: bias, round to fp16, x tiles into [0,32K) ----
    // x cc0 @0, x cc1 @16K
    #pragma unroll
    for (int mt = 0; mt < 2; mt++) {
        #pragma unroll
        for (int nt = 0; nt < 8; nt++) {
            int n = n0 + nt * 8 + (lane & 3) * 2;
            float b0v = conv_b[n], b1v = conv_b[n + 1];
            uint32_t tbase = (uint32_t)((n >> 6) * 16384);
            #pragma unroll
            for (int half = 0; half < 2; half++) {
                int mrow = m0 + mt * 16 + (lane >> 2) + half * 8;
                float v0 = acc[mt][nt][half * 2 + 0] + b0v;
                float v1 = acc[mt][nt][half * 2 + 1] + b1v;
                uint32_t off = SW(mrow * 128 + (n & 63) * 2);
                *(uint32_t*)(smem + tbase + off) = pack2h(__float2half(v0), __float2half(v1));
            }
        }
    }
    CP_WAIT(0);
    __syncthreads();

    // ---- projections: out[m][k] = sum_c x[m][c] * w[k][c] + bias ----
    const size_t mg = (size_t)bb * HW + (size_t)y * Wdim;
    #pragma unroll 1
    for (int tg = 0; tg < 2; tg++) {
        #pragma unroll
        for (int mt = 0; mt < 2; mt++)
            #pragma unroll
            for (int nt = 0; nt < 8; nt++)
                #pragma unroll
                for (int e = 0; e < 4; e++) acc[mt][nt][e] = 0.f;

        uint32_t wbase = sb0 + 32768u + (uint32_t)tg * 32768u;
        #pragma unroll
        for (int cc = 0; cc < 2; cc++) {
            compute_tile1(acc, sb0 + cc * 16384u, wbase + cc * 16384u, m0, n0, lane);
        }

        const float* bias = tg ? query_b : key_b;
        #pragma unroll
        for (int mt = 0; mt < 2; mt++) {
            #pragma unroll
            for (int nt = 0; nt < 8; nt++) {
                int n = n0 + nt * 8 + (lane & 3) * 2;
                float b0v = bias[n], b1v = bias[n + 1];
                #pragma unroll
                for (int half = 0; half < 2; half++) {
                    int mrow = m0 + mt * 16 + (lane >> 2) + half * 8;
                    float v0 = acc[mt][nt][half * 2 + 0] + b0v;
                    float v1 = acc[mt][nt][half * 2 + 1] + b1v;
                    size_t o = (mg + mrow) * KQ + n;
                    if (tg) {
                        *(float2*)&g_qrs[o] = make_float2(v0, v1);
                    } else {
                        *(uint32_t*)&g_keys_h[o] = pack2h(__float2half(v0), __float2half(v1));
                    }
                }
            }
        }
    }
}

// ---------------- combined avg pool: z=0 queries(fp32), z=1 keys(fp16) ----------------
__global__ __launch_bounds__(256) void pool_all() {
    int idx = blockIdx.x * 256 + threadIdx.x;
    int s;
    if (idx < B_ * 4096 * 32) { s = 2; }
    else { s = 4; idx -= B_ * 4096 * 32; if (idx >= B_ * 1024 * 32) return; }
    const int hp = Hdim / s;
    const int n  = hp * hp;
    int c4 = idx & 31;
    int nn = (idx >> 5) % n;
    int b  = idx / (n * 32);
    int yy = nn / hp, xx = nn % hp;

    if (blockIdx.z == 0) {
        const float* in = g_qrs;
        float* out = (s == 2) ? g_q2 : g_q4;
        float4 acc = make_float4(0.f, 0.f, 0.f, 0.f);
        for (int ry = 0; ry < s; ry++)
            for (int rx = 0; rx < s; rx++) {
                int m = (yy * s + ry) * Wdim + xx * s + rx;
                float4 v = *(const float4*)&in[((size_t)b * HW + m) * KQ + c4 * 4];
                acc.x += v.x; acc.y += v.y; acc.z += v.z; acc.w += v.w;
            }
        float inv = 1.f / (float)(s * s);
        acc.x *= inv; acc.y *= inv; acc.z *= inv; acc.w *= inv;
        *(float4*)&out[((size_t)b * n + nn) * KQ + c4 * 4] = acc;
    } else {
        const __half* in = g_keys_h;
        __half* out = (s == 2) ? g_k2_h : g_k4_h;
        float a0 = 0.f, a1 = 0.f, a2 = 0.f, a3 = 0.f;
        for (int ry = 0; ry < s; ry++)
            for (int rx = 0; rx < s; rx++) {
                int m = (yy * s + ry) * Wdim + xx * s + rx;
                uint2 v = *(const uint2*)&in[((size_t)b * HW + m) * KQ + c4 * 4];
                a0 += lo_half(v.x); a1 += hi_half(v.x);
                a2 += lo_half(v.y); a3 += hi_half(v.y);
            }
        float inv = 1.f / (float)(s * s);
        uint2 r;
        r.x = pack2h(__float2half(a0 * inv), __float2half(a1 * inv));
        r.y = pack2h(__float2half(a2 * inv), __float2half(a3 * inv));
        *(uint2*)&out[((size_t)b * n + nn) * KQ + c4 * 4] = r;
    }
}

// ---------------- logits: all levels, MLP=32 gather ----------------
__global__ __launch_bounds__(256) void logits_all(const int* __restrict__ si2,
                                                  const int* __restrict__ si3,
                                                  const int* __restrict__ si4,
                                                  float* __restrict__ out) {
    int bx = blockIdx.x;
    const float* q;
    const __half* k;
    const int* inds;
    int n, n_off, lbase;
    if (bx < 2048)      { q = g_qrs; k = g_keys_h; inds = si2; n = 16384; n_off = 0;     lbase = bx; }
    else if (bx < 2560) { q = g_q2;  k = g_k2_h;   inds = si3; n = 4096;  n_off = 16384; lbase = bx - 2048; }
    else                { q = g_q4;  k = g_k4_h;   inds = si4; n = 1024;  n_off = 20480; lbase = bx - 2560; }

    const int warp = threadIdx.x >> 5;
    const int lane = threadIdx.x & 31;
    const int nn = lbase * 8 + warp;
    const int b  = blockIdx.z;

    float4 qv = *(const float4*)&q[((size_t)b * n + nn) * KQ + lane * 4];
    int myind = inds[((size_t)b * n + nn) * 32 + lane];

    const __half* kb = k + (size_t)b * n * KQ;
    uint2 kv[32];
    #pragma unroll
    for (int s = 0; s < 32; s++) {
        int ind = __shfl_sync(0xffffffffu, myind, s);
        kv[s] = *(const uint2*)&kb[(size_t)ind * KQ + lane * 4];
    }

    float myval = 0.f;
    #pragma unroll
    for (int s = 0; s < 32; s++) {
        float p = qv.x * lo_half(kv[s].x) + qv.y * hi_half(kv[s].x)
                + qv.z * lo_half(kv[s].y) + qv.w * hi_half(kv[s].y);
        p += __shfl_xor_sync(0xffffffffu, p, 1);
        p += __shfl_xor_sync(0xffffffffu, p, 2);
        p += __shfl_xor_sync(0xffffffffu, p, 4);
        p += __shfl_xor_sync(0xffffffffu, p, 8);
        p += __shfl_xor_sync(0xffffffffu, p, 16);
        if (lane == s) myval = p * SCALE;
    }
    out[((size_t)b * NTOT + n_off + nn) * 32 + lane] = myval;
}

// ---------------- launch ----------------
extern "C" void kernel_launch(void* const* d_in, const int* in_sizes, int n_in,
                              void* d_out, int out_size) {
    const float* feats   = (const float*)d_in[0];
    const float* conv_w  = (const float*)d_in[1];
    const float* conv_b  = (const float*)d_in[2];
    const float* key_w   = (const float*)d_in[3];
    const float* key_b   = (const float*)d_in[4];
    const float* query_w = (const float*)d_in[5];
    const float* query_b = (const float*)d_in[6];
    const int* si2 = (const int*)d_in[7];
    const int* si3 = (const int*)d_in[8];
    const int* si4 = (const int*)d_in[9];
    float* out = (float*)d_out;

    static bool attr_set = false;
    if (!attr_set) {
        cudaFuncSetAttribute(conv_fused, cudaFuncAttributeMaxDynamicSharedMemorySize, SMEM_BYTES);
        attr_set = true;
    }

    zero_border_kernel<<<(B_ * 516 * 32 + 255) / 256, 256>>>();
    transpose_cv<<<8192, 256>>>(feats);
    prep_w2<<<(9 * KQ * CIN + 255) / 256, 256>>>(conv_w, key_w, query_w);
    conv_fused<<<dim3(Hdim, B_), 256, SMEM_BYTES>>>(conv_b, key_b, query_b);
    pool_all<<<dim3((B_ * (4096 + 1024) * 32 + 255) / 256, 1, 2), 256>>>();
    logits_all<<<dim3(2688, 1, B_), 256>>>(si2, si3, si4, out);
}

// round 16
// speedup vs baseline: 1.6235x; 1.0588x over previous
#include <cuda_runtime.h>
#include <cuda_fp16.h>
#include <cstdint>

#define B_      2
#define CIN     256
#define Hdim    128
#define Wdim    128
#define KQ      128
#define HW      16384
#define NTOT    21504   // 16384 + 4096 + 1024
#define SCALE   0.08838834764831845f
#define PADW    130
#define PADN    16900   // 130*130

#define SMEM_BYTES 98304   // 3 stages x 32KB
#define SW(o) ((uint32_t)(o) ^ ((((uint32_t)(o)) >> 3) & 0x70u))

// ---------------- device scratch ----------------
__device__ __half g_fp_hi[B_ * PADN * CIN];        // padded feats, fp16
__device__ __half g_w_hi[9 * KQ * CIN];
__device__ __half g_kw_hi[KQ * KQ];
__device__ __half g_qw_hi[KQ * KQ];
__device__ __half g_keys_h[B_ * HW * KQ];          // keys fp16 (gathered by logits)
__device__ float  g_qrs[B_ * HW * KQ];             // queries fp32
__device__ __half g_k2_h[B_ * 4096 * KQ], g_k4_h[B_ * 1024 * KQ];
__device__ float  g_q2[B_ * 4096 * KQ],  g_q4[B_ * 1024 * KQ];

// ---------------- helpers ----------------
__device__ __forceinline__ uint32_t smem_u32(const void* p) {
    uint32_t a;
    asm("{ .reg .u64 t; cvta.to.shared.u64 t, %1; cvt.u32.u64 %0, t; }" : "=r"(a) : "l"(p));
    return a;
}
__device__ __forceinline__ void cp16(uint32_t dst, const void* src) {
    asm volatile("cp.async.cg.shared.global [%0], [%1], 16;" :: "r"(dst), "l"(src) : "memory");
}
#define CP_COMMIT() asm volatile("cp.async.commit_group;" ::: "memory")
#define CP_WAIT(n)  asm volatile("cp.async.wait_group %0;" :: "n"(n) : "memory")

__device__ __forceinline__ void ldsm_x4(uint32_t* r, uint32_t addr) {
    asm volatile("ldmatrix.sync.aligned.m8n8.x4.shared.b16 {%0,%1,%2,%3}, [%4];"
                 : "=r"(r[0]), "=r"(r[1]), "=r"(r[2]), "=r"(r[3]) : "r"(addr));
}
__device__ __forceinline__ void ldsm_x2(uint32_t* r, uint32_t addr) {
    asm volatile("ldmatrix.sync.aligned.m8n8.x2.shared.b16 {%0,%1}, [%2];"
                 : "=r"(r[0]), "=r"(r[1]) : "r"(addr));
}
// fp16 inputs, fp32 accumulator
__device__ __forceinline__ void mma_f32(float* c, const uint32_t* a, const uint32_t* b) {
    asm volatile("mma.sync.aligned.m16n8k16.row.col.f32.f16.f16.f32 "
                 "{%0,%1,%2,%3}, {%4,%5,%6,%7}, {%8,%9}, {%0,%1,%2,%3};"
                 : "+f"(c[0]), "+f"(c[1]), "+f"(c[2]), "+f"(c[3])
                 : "r"(a[0]), "r"(a[1]), "r"(a[2]), "r"(a[3]), "r"(b[0]), "r"(b[1]));
}
__device__ __forceinline__ uint32_t pack2h(__half a, __half b) {
    return (uint32_t)__half_as_ushort(a) | ((uint32_t)__half_as_ushort(b) << 16);
}
__device__ __forceinline__ float lo_half(uint32_t r) {
    return __half2float(__ushort_as_half((unsigned short)(r & 0xffffu)));
}
__device__ __forceinline__ float hi_half(uint32_t r) {
    return __half2float(__ushort_as_half((unsigned short)(r >> 16)));
}

// Stage 2 tiles (A, B), each [128 rows x 64 fp16] SW128-swizzled. 32KB total.
__device__ __forceinline__ void stage_tiles(uint32_t sdst,
    const __half* a, const __half* b,
    int a_stride, int b_stride, int tid)
{
    #pragma unroll
    for (int s = 0; s < 8; s++) {
        int i = tid + s * 256;
        int tile = i >> 10, j = i & 1023, r = j >> 3, c16 = j & 7;
        const __half* src = tile ? (b + (size_t)r * b_stride) : (a + (size_t)r * a_stride);
        cp16(sdst + tile * 16384 + SW(r * 128 + c16 * 16), src + c16 * 8);
    }
}

// One 128x128x64 GEMM step, pure fp16 inputs, fp32 acc.
// B fragments held 4-at-a-time; A fragment loaded per-mt: minimal live set.
__device__ __forceinline__ void compute_tile1(float acc[2][8][4],
    uint32_t a_t, uint32_t b_t, int m0, int n0, int lane)
{
    #pragma unroll
    for (int ks = 0; ks < 4; ks++) {
        const int bro = (n0 + (lane & 7)) * 128 + ks * 32 + ((lane >> 3) & 1) * 16;
        const int aro = (m0 + (lane & 15)) * 128 + ks * 32 + (lane >> 4) * 16;
        #pragma unroll
        for (int nh = 0; nh < 2; nh++) {
            uint32_t bh[4][2];
            #pragma unroll
            for (int t = 0; t < 4; t++)
                ldsm_x2(bh[t], b_t + SW(bro + (nh * 4 + t) * 1024));
            #pragma unroll
            for (int mt = 0; mt < 2; mt++) {
                uint32_t ah[4];
                ldsm_x4(ah, a_t + SW(aro + mt * 2048));
                #pragma unroll
                for (int t = 0; t < 4; t++)
                    mma_f32(acc[mt][nh * 4 + t], ah, bh[t]);
            }
        }
    }
}

// ---------------- prep kernels ----------------
__global__ __launch_bounds__(256) void zero_border_kernel() {
    int idx = blockIdx.x * 256 + threadIdx.x;
    const int per_b = 516 * 32;
    if (idx >= B_ * per_b) return;
    int b = idx / per_b;
    int r = idx % per_b;
    int cell = r >> 5;
    int cgrp = r & 31;
    int y, x;
    if (cell < 130)      { y = 0;   x = cell; }
    else if (cell < 260) { y = 129; x = cell - 130; }
    else if (cell < 388) { y = 1 + (cell - 260); x = 0; }
    else                 { y = 1 + (cell - 388); x = 129; }
    size_t o = ((size_t)b * PADN + (size_t)y * PADW + x) * CIN + cgrp * 8;
    *(float4*)&g_fp_hi[o] = make_float4(0.f, 0.f, 0.f, 0.f);
}

__global__ __launch_bounds__(256) void transpose_cv(const float* __restrict__ feats) {
    __shared__ float s[32][33];
    int bid = blockIdx.x;
    int cblk = bid & 7;
    int xblk = (bid >> 3) & 3;
    int y    = (bid >> 5) & 127;
    int b    = bid >> 12;
    int c0 = cblk * 32, x0 = xblk * 32;
    int tid = threadIdx.x;

    #pragma unroll
    for (int r = 0; r < 4; r++) {
        int ci = (tid >> 5) + r * 8;
        int xi = tid & 31;
        s[ci][xi] = feats[(((size_t)b * CIN + c0 + ci) * Hdim + y) * Wdim + x0 + xi];
    }
    __syncthreads();
    #pragma unroll
    for (int r = 0; r < 4; r++) {
        int xj = (tid >> 5) + r * 8;
        int cj = tid & 31;
        size_t idx = ((size_t)b * PADN + (size_t)(y + 1) * PADW + (x0 + xj + 1)) * CIN + c0 + cj;
        g_fp_hi[idx] = __float2half(s[cj][xj]);
    }
}

__global__ __launch_bounds__(256) void prep_w2(const float* __restrict__ conv_w,
                                               const float* __restrict__ key_w,
                                               const float* __restrict__ query_w) {
    int i = blockIdx.x * 256 + threadIdx.x;
    if (i < 9 * KQ * CIN) {
        int t = i / (KQ * CIN);
        int rem = i % (KQ * CIN);
        int k = rem / CIN, c = rem % CIN;
        g_w_hi[i] = __float2half(conv_w[((size_t)k * CIN + c) * 9 + t]);
    }
    if (i < KQ * KQ) {
        g_kw_hi[i] = __float2half(key_w[i]);
        g_qw_hi[i] = __float2half(query_w[i]);
    }
}

// ---------------- fused conv3x3 + projections, pure fp16 GEMM ----------------
// CTA = 256 threads, one (b, y). K = 9x256 in 36 chunks of 64; 3-stage (32KB)
// pipeline; 2 CTAs/SM (96KB smem, <=128 regs). x kept in SMEM for projections.
__global__ __launch_bounds__(256, 2) void conv_fused(const float* __restrict__ conv_b,
                                                     const float* __restrict__ key_b,
                                                     const float* __restrict__ query_b) {
    extern __shared__ char smem[];
    const uint32_t sb0 = smem_u32(smem);
    const int tid = threadIdx.x, warp = tid >> 5, lane = tid & 31;
    const int y = blockIdx.x, bb = blockIdx.y;
    const int m0 = (warp & 3) * 32, n0 = (warp >> 2) * 64;

    float acc[2][8][4];
    #pragma unroll
    for (int mt = 0; mt < 2; mt++)
        #pragma unroll
        for (int nt = 0; nt < 8; nt++)
            #pragma unroll
            for (int e = 0; e < 4; e++) acc[mt][nt][e] = 0.f;

    const size_t apb = (size_t)bb * PADN;

    #pragma unroll 1
    for (int nid = 0; nid < 2; nid++) {
        int tap = nid >> 2, cc = nid & 3;
        int dy = tap / 3, dx = tap % 3;
        size_t arow = (apb + (size_t)(y + dy) * PADW + dx) * CIN + cc * 64;
        size_t wrow = (size_t)tap * KQ * CIN + cc * 64;
        stage_tiles(sb0 + (uint32_t)(nid % 3) * 32768u,
                    g_fp_hi + arow, g_w_hi + wrow, CIN, CIN, tid);
        CP_COMMIT();
    }

    #pragma unroll 1
    for (int idx = 0; idx < 36; idx++) {
        CP_WAIT(1);
        __syncthreads();
        int nid = idx + 2;
        if (nid < 36) {
            int tap = nid >> 2, cc = nid & 3;
            int dy = tap / 3, dx = tap % 3;
            size_t arow = (apb + (size_t)(y + dy) * PADW + dx) * CIN + cc * 64;
            size_t wrow = (size_t)tap * KQ * CIN + cc * 64;
            stage_tiles(sb0 + (uint32_t)(nid % 3) * 32768u,
                        g_fp_hi + arow, g_w_hi + wrow, CIN, CIN, tid);
        }
        CP_COMMIT();
        uint32_t tb = sb0 + (uint32_t)(idx % 3) * 32768u;
        compute_tile1(acc, tb, tb + 16384, m0, n0, lane);
    }
    __syncthreads();   // all compute done; stage buffers free

    // ---- issue proj-weight loads: kw @[32K,64K), qw @[64K,96K) (2 cc tiles each) ----
    #pragma unroll
    for (int s = 0; s < 16; s++) {
        int i = tid + s * 256;
        int tile = i >> 10, j = i & 1023, r = j >> 3, c16 = j & 7;
        int tg = tile >> 1, cc = tile & 1;
        const __half* src = (tg ? g_qw_hi : g_kw_hi) + (size_t)r * KQ + cc * 64 + c16 * 8;
        cp16(sb0 + 32768u + tile * 16384u + SW(r * 128 + c16 * 16), src);
    }
    CP_COMMIT();

    // ---- conv epilogue: bias, round to fp16, x tiles into [0,32K) ----
    // x cc0 @0, x cc1 @16K
    #pragma unroll
    for (int mt = 0; mt < 2; mt++) {
        #pragma unroll
        for (int nt = 0; nt < 8; nt++) {
            int n = n0 + nt * 8 + (lane & 3) * 2;
            float b0v = conv_b[n], b1v = conv_b[n + 1];
            uint32_t tbase = (uint32_t)((n >> 6) * 16384);
            #pragma unroll
            for (int half = 0; half < 2; half++) {
                int mrow = m0 + mt * 16 + (lane >> 2) + half * 8;
                float v0 = acc[mt][nt][half * 2 + 0] + b0v;
                float v1 = acc[mt][nt][half * 2 + 1] + b1v;
                uint32_t off = SW(mrow * 128 + (n & 63) * 2);
                *(uint32_t*)(smem + tbase + off) = pack2h(__float2half(v0), __float2half(v1));
            }
        }
    }
    CP_WAIT(0);
    __syncthreads();

    // ---- projections: out[m][k] = sum_c x[m][c] * w[k][c] + bias ----
    const size_t mg = (size_t)bb * HW + (size_t)y * Wdim;
    #pragma unroll 1
    for (int tg = 0; tg < 2; tg++) {
        #pragma unroll
        for (int mt = 0; mt < 2; mt++)
            #pragma unroll
            for (int nt = 0; nt < 8; nt++)
                #pragma unroll
                for (int e = 0; e < 4; e++) acc[mt][nt][e] = 0.f;

        uint32_t wbase = sb0 + 32768u + (uint32_t)tg * 32768u;
        #pragma unroll
        for (int cc = 0; cc < 2; cc++) {
            compute_tile1(acc, sb0 + cc * 16384u, wbase + cc * 16384u, m0, n0, lane);
        }

        const float* bias = tg ? query_b : key_b;
        #pragma unroll
        for (int mt = 0; mt < 2; mt++) {
            #pragma unroll
            for (int nt = 0; nt < 8; nt++) {
                int n = n0 + nt * 8 + (lane & 3) * 2;
                float b0v = bias[n], b1v = bias[n + 1];
                #pragma unroll
                for (int half = 0; half < 2; half++) {
                    int mrow = m0 + mt * 16 + (lane >> 2) + half * 8;
                    float v0 = acc[mt][nt][half * 2 + 0] + b0v;
                    float v1 = acc[mt][nt][half * 2 + 1] + b1v;
                    size_t o = (mg + mrow) * KQ + n;
                    if (tg) {
                        *(float2*)&g_qrs[o] = make_float2(v0, v1);
                    } else {
                        *(uint32_t*)&g_keys_h[o] = pack2h(__float2half(v0), __float2half(v1));
                    }
                }
            }
        }
    }
}

// ---------------- combined avg pool: z=0 queries(fp32), z=1 keys(fp16) ----------------
__global__ __launch_bounds__(256) void pool_all() {
    int idx = blockIdx.x * 256 + threadIdx.x;
    int s;
    if (idx < B_ * 4096 * 32) { s = 2; }
    else { s = 4; idx -= B_ * 4096 * 32; if (idx >= B_ * 1024 * 32) return; }
    const int hp = Hdim / s;
    const int n  = hp * hp;
    int c4 = idx & 31;
    int nn = (idx >> 5) % n;
    int b  = idx / (n * 32);
    int yy = nn / hp, xx = nn % hp;

    if (blockIdx.z == 0) {
        const float* in = g_qrs;
        float* out = (s == 2) ? g_q2 : g_q4;
        float4 acc = make_float4(0.f, 0.f, 0.f, 0.f);
        for (int ry = 0; ry < s; ry++)
            for (int rx = 0; rx < s; rx++) {
                int m = (yy * s + ry) * Wdim + xx * s + rx;
                float4 v = *(const float4*)&in[((size_t)b * HW + m) * KQ + c4 * 4];
                acc.x += v.x; acc.y += v.y; acc.z += v.z; acc.w += v.w;
            }
        float inv = 1.f / (float)(s * s);
        acc.x *= inv; acc.y *= inv; acc.z *= inv; acc.w *= inv;
        *(float4*)&out[((size_t)b * n + nn) * KQ + c4 * 4] = acc;
    } else {
        const __half* in = g_keys_h;
        __half* out = (s == 2) ? g_k2_h : g_k4_h;
        float a0 = 0.f, a1 = 0.f, a2 = 0.f, a3 = 0.f;
        for (int ry = 0; ry < s; ry++)
            for (int rx = 0; rx < s; rx++) {
                int m = (yy * s + ry) * Wdim + xx * s + rx;
                uint2 v = *(const uint2*)&in[((size_t)b * HW + m) * KQ + c4 * 4];
                a0 += lo_half(v.x); a1 += hi_half(v.x);
                a2 += lo_half(v.y); a3 += hi_half(v.y);
            }
        float inv = 1.f / (float)(s * s);
        uint2 r;
        r.x = pack2h(__float2half(a0 * inv), __float2half(a1 * inv));
        r.y = pack2h(__float2half(a2 * inv), __float2half(a3 * inv));
        *(uint2*)&out[((size_t)b * n + nn) * KQ + c4 * 4] = r;
    }
}

// ---------------- logits: all levels, MLP=32 gather ----------------
__global__ __launch_bounds__(256) void logits_all(const int* __restrict__ si2,
                                                  const int* __restrict__ si3,
                                                  const int* __restrict__ si4,
                                                  float* __restrict__ out) {
    int bx = blockIdx.x;
    const float* q;
    const __half* k;
    const int* inds;
    int n, n_off, lbase;
    if (bx < 2048)      { q = g_qrs; k = g_keys_h; inds = si2; n = 16384; n_off = 0;     lbase = bx; }
    else if (bx < 2560) { q = g_q2;  k = g_k2_h;   inds = si3; n = 4096;  n_off = 16384; lbase = bx - 2048; }
    else                { q = g_q4;  k = g_k4_h;   inds = si4; n = 1024;  n_off = 20480; lbase = bx - 2560; }

    const int warp = threadIdx.x >> 5;
    const int lane = threadIdx.x & 31;
    const int nn = lbase * 8 + warp;
    const int b  = blockIdx.z;

    float4 qv = *(const float4*)&q[((size_t)b * n + nn) * KQ + lane * 4];
    int myind = inds[((size_t)b * n + nn) * 32 + lane];

    const __half* kb = k + (size_t)b * n * KQ;
    uint2 kv[32];
    #pragma unroll
    for (int s = 0; s < 32; s++) {
        int ind = __shfl_sync(0xffffffffu, myind, s);
        kv[s] = *(const uint2*)&kb[(size_t)ind * KQ + lane * 4];
    }

    float myval = 0.f;
    #pragma unroll
    for (int s = 0; s < 32; s++) {
        float p = qv.x * lo_half(kv[s].x) + qv.y * hi_half(kv[s].x)
                + qv.z * lo_half(kv[s].y) + qv.w * hi_half(kv[s].y);
        p += __shfl_xor_sync(0xffffffffu, p, 1);
        p += __shfl_xor_sync(0xffffffffu, p, 2);
        p += __shfl_xor_sync(0xffffffffu, p, 4);
        p += __shfl_xor_sync(0xffffffffu, p, 8);
        p += __shfl_xor_sync(0xffffffffu, p, 16);
        if (lane == s) myval = p * SCALE;
    }
    out[((size_t)b * NTOT + n_off + nn) * 32 + lane] = myval;
}

// ---------------- launch ----------------
extern "C" void kernel_launch(void* const* d_in, const int* in_sizes, int n_in,
                              void* d_out, int out_size) {
    const float* feats   = (const float*)d_in[0];
    const float* conv_w  = (const float*)d_in[1];
    const float* conv_b  = (const float*)d_in[2];
    const float* key_w   = (const float*)d_in[3];
    const float* key_b   = (const float*)d_in[4];
    const float* query_w = (const float*)d_in[5];
    const float* query_b = (const float*)d_in[6];
    const int* si2 = (const int*)d_in[7];
    const int* si3 = (const int*)d_in[8];
    const int* si4 = (const int*)d_in[9];
    float* out = (float*)d_out;

    static bool attr_set = false;
    if (!attr_set) {
        cudaFuncSetAttribute(conv_fused, cudaFuncAttributeMaxDynamicSharedMemorySize, SMEM_BYTES);
        attr_set = true;
    }

    zero_border_kernel<<<(B_ * 516 * 32 + 255) / 256, 256>>>();
    transpose_cv<<<8192, 256>>>(feats);
    prep_w2<<<(9 * KQ * CIN + 255) / 256, 256>>>(conv_w, key_w, query_w);
    conv_fused<<<dim3(Hdim, B_), 256, SMEM_BYTES>>>(conv_b, key_b, query_b);
    pool_all<<<dim3((B_ * (4096 + 1024) * 32 + 255) / 256, 1, 2), 256>>>();
    logits_all<<<dim3(2688, 1, B_), 256>>>(si2, si3, si4, out);
}